// round 6
// baseline (speedup 1.0000x reference)
#include <cuda_runtime.h>
#include <cstdint>

// SpiralConv gather-GEMM, mma.sync TF32. R6: 4 warps/CTA, 64x64 warp tiles,
// 3-stage cp.async pipeline, fragment-native gmem layout + parity swizzle.
// out[m,o] = relu(sum_k A[m,k]*W[o,k] + b[o]) * zp[m%N]; M=96000, K=2048, N=128.

constexpr int Bq = 8, Nq = 12000, Fq = 128, Sq = 16, OUTq = 128;
constexpr int Kq = Sq * Fq;       // 2048
constexpr int Mtot = Bq * Nq;     // 96000
constexpr int BM = 128;
constexpr int NITER = Kq / 32;    // 64 (BK=32)
constexpr int NST = 3;

// Pre-rounded (TF32-RNE), per-32-group permuted copies:
// slot s (float4) of each 32-float group holds k = {(s&3)+16*(s>>2)} + 4j, j=0..3.
__device__ float g_x[Bq * Nq * Fq];
__device__ float g_w[OUTq * Kq];

// smem layout (bytes). A/B rows are exactly 128B; chunk swizzle ^ (4*(row&1)).
constexpr int STG = BM * 128;                       // 16384 per tile stage
constexpr int OFF_A = 0;                            // 3 stages
constexpr int OFF_B = OFF_A + NST * STG;            // 49152
constexpr int OFF_ATAB = OFF_B + NST * STG;         // 98304 (128*16 uint32)
constexpr int OFF_BIAS = OFF_ATAB + BM * Sq * 4;    // 106496
constexpr int SMEM_BYTES = OFF_BIAS + OUTq * 4;     // 107008

__device__ __forceinline__ float tf32_rne(float f) {
    uint32_t u;
    asm("cvt.rna.tf32.f32 %0, %1;" : "=r"(u) : "f"(f));
    return __uint_as_float(u);
}

__device__ __forceinline__ void cp_async16(void* sdst, const void* gsrc) {
    unsigned d = (unsigned)__cvta_generic_to_shared(sdst);
    asm volatile("cp.async.cg.shared.global [%0], [%1], 16;" :: "r"(d), "l"(gsrc));
}

// ---- prepass: one thread per 32-float group; TF32 round + fragment permute ----
__global__ void prep_kernel(const float* __restrict__ x, const float* __restrict__ W,
                            int xgroups, int totgroups) {
    int g = blockIdx.x * 256 + threadIdx.x;
    if (g >= totgroups) return;
    const float4* src;
    float4* dst;
    int lg = g;
    if (g < xgroups) { src = (const float4*)x; dst = (float4*)g_x; }
    else { src = (const float4*)W; dst = (float4*)g_w; lg = g - xgroups; }
    float v[32];
    #pragma unroll
    for (int j = 0; j < 8; ++j) {
        float4 t = src[lg * 8 + j];
        v[j * 4 + 0] = tf32_rne(t.x);
        v[j * 4 + 1] = tf32_rne(t.y);
        v[j * 4 + 2] = tf32_rne(t.z);
        v[j * 4 + 3] = tf32_rne(t.w);
    }
    #pragma unroll
    for (int s = 0; s < 8; ++s) {
        int c0 = (s & 3) + ((s >> 2) << 4);
        dst[lg * 8 + s] = make_float4(v[c0], v[c0 + 4], v[c0 + 8], v[c0 + 12]);
    }
}

extern __shared__ char smem[];

__global__ __launch_bounds__(128, 2) void spiral_mma_kernel(
    const float* __restrict__ bias,
    const int*   __restrict__ adj,   // [N, S]
    const float* __restrict__ zp,    // [N]
    float*       __restrict__ out)   // [Mtot, OUT]
{
    const int tid = threadIdx.x;
    const int m0 = blockIdx.x * BM;

    uint32_t* atab  = reinterpret_cast<uint32_t*>(smem + OFF_ATAB);
    float*    sbias = reinterpret_cast<float*>(smem + OFF_BIAS);

    // gather-address table: byte offset of x-row (b*Nq+idx) for each (row, s)
    for (int i = tid; i < BM * Sq; i += 128) {
        int r = i >> 4, s = i & 15;
        int mm = m0 + r;
        int b = mm / Nq, n = mm - b * Nq;
        atab[i] = (uint32_t)(b * Nq + adj[n * Sq + s]) << 9;   // *512 bytes
    }
    sbias[tid] = bias[tid];
    __syncthreads();

    // loader: thread covers rows lr+16j (j=0..7), 16B chunk slot lc
    const int lr = tid >> 3;          // 0..15
    const int lc = tid & 7;
    const uint32_t* atp = atab + lr * 16;   // + 256*j + sidx
    int adst[8];
    const char* wsrc[8];
    #pragma unroll
    for (int j = 0; j < 8; ++j) {
        int row = lr + j * 16;
        adst[j] = row * 128 + ((lc ^ ((row & 1) << 2)) << 4);
        wsrc[j] = reinterpret_cast<const char*>(g_w) + row * (Kq * 4) + lc * 16;
    }

    auto load_stage = [&](int st, int it2) {
        const int sidx = it2 >> 2;
        const char* gx = reinterpret_cast<const char*>(g_x) + ((it2 & 3) << 7) + lc * 16;
        char* abase = smem + OFF_A + st * STG;
        char* bbase = smem + OFF_B + st * STG;
        const int wadv = it2 << 7;
        #pragma unroll
        for (int j = 0; j < 8; ++j)
            cp_async16(abase + adst[j], gx + atp[256 * j + sidx]);
        #pragma unroll
        for (int j = 0; j < 8; ++j)
            cp_async16(bbase + adst[j], wsrc[j] + wadv);
    };

    load_stage(0, 0); asm volatile("cp.async.commit_group;");
    load_stage(1, 1); asm volatile("cp.async.commit_group;");

    const int lane = tid & 31;
    const int warp = tid >> 5;
    const int wm = (warp & 1) * 64;   // 2 warps over M (64 rows each)
    const int wn = (warp >> 1) * 64;  // 2 warps over N (64 cols each)
    const int tr = lane >> 2;
    const int tc = lane & 3;
    const int swz = (tr & 1) << 2;

    float acc[4][8][4];
    #pragma unroll
    for (int a = 0; a < 4; ++a)
        #pragma unroll
        for (int b2 = 0; b2 < 8; ++b2)
            #pragma unroll
            for (int c = 0; c < 4; ++c) acc[a][b2][c] = 0.f;

    int cur = 0, nx2 = 2;
    for (int it = 0; it < NITER; ++it) {
        asm volatile("cp.async.wait_group 1;");
        __syncthreads();

        // refill the buffer consumed at iter it-1 with stage it+2
        if (it + 2 < NITER) load_stage(nx2, it + 2);
        asm volatile("cp.async.commit_group;");

        const float4* A4 = reinterpret_cast<const float4*>(smem + OFF_A + cur * STG);
        const float4* B4 = reinterpret_cast<const float4*>(smem + OFF_B + cur * STG);

        #pragma unroll
        for (int h = 0; h < 2; ++h) {
            const int chunk = (tc + 4 * h) ^ swz;
            float4 bfr[8];
            #pragma unroll
            for (int nt = 0; nt < 8; ++nt)
                bfr[nt] = B4[(wn + nt * 8 + tr) * 8 + chunk];
            #pragma unroll
            for (int mt = 0; mt < 4; ++mt) {
                const int r = wm + mt * 16 + tr;
                float4 alo = A4[r * 8 + chunk];
                float4 ahi = A4[(r + 8) * 8 + chunk];
                uint32_t a0 = __float_as_uint(alo.x), a1 = __float_as_uint(ahi.x);
                uint32_t a2 = __float_as_uint(alo.y), a3 = __float_as_uint(ahi.y);
                #pragma unroll
                for (int nt = 0; nt < 8; ++nt)
                    asm volatile(
                        "mma.sync.aligned.m16n8k8.row.col.f32.tf32.tf32.f32 "
                        "{%0,%1,%2,%3}, {%4,%5,%6,%7}, {%8,%9}, {%0,%1,%2,%3};"
                        : "+f"(acc[mt][nt][0]), "+f"(acc[mt][nt][1]),
                          "+f"(acc[mt][nt][2]), "+f"(acc[mt][nt][3])
                        : "r"(a0), "r"(a1), "r"(a2), "r"(a3),
                          "r"(__float_as_uint(bfr[nt].x)), "r"(__float_as_uint(bfr[nt].y)));
                uint32_t c0 = __float_as_uint(alo.z), c1 = __float_as_uint(ahi.z);
                uint32_t c2 = __float_as_uint(alo.w), c3 = __float_as_uint(ahi.w);
                #pragma unroll
                for (int nt = 0; nt < 8; ++nt)
                    asm volatile(
                        "mma.sync.aligned.m16n8k8.row.col.f32.tf32.tf32.f32 "
                        "{%0,%1,%2,%3}, {%4,%5,%6,%7}, {%8,%9}, {%0,%1,%2,%3};"
                        : "+f"(acc[mt][nt][0]), "+f"(acc[mt][nt][1]),
                          "+f"(acc[mt][nt][2]), "+f"(acc[mt][nt][3])
                        : "r"(c0), "r"(c1), "r"(c2), "r"(c3),
                          "r"(__float_as_uint(bfr[nt].z)), "r"(__float_as_uint(bfr[nt].w)));
            }
        }

        cur = (cur == NST - 1) ? 0 : cur + 1;
        nx2 = (nx2 == NST - 1) ? 0 : nx2 + 1;
    }

    // ---- epilogue: bias + relu + zero_padding ----
    #pragma unroll
    for (int mt = 0; mt < 4; ++mt) {
        #pragma unroll
        for (int hh = 0; hh < 2; ++hh) {
            int m = m0 + wm + mt * 16 + hh * 8 + tr;
            float z = zp[m % Nq];
            float* orow = out + (long)m * OUTq;
            #pragma unroll
            for (int nt = 0; nt < 8; ++nt) {
                int o = wn + nt * 8 + 2 * tc;
                float v0 = fmaxf(acc[mt][nt][hh * 2 + 0] + sbias[o], 0.f) * z;
                float v1 = fmaxf(acc[mt][nt][hh * 2 + 1] + sbias[o + 1], 0.f) * z;
                *reinterpret_cast<float2*>(orow + o) = make_float2(v0, v1);
            }
        }
    }
}

extern "C" void kernel_launch(void* const* d_in, const int* in_sizes, int n_in,
                              void* d_out, int out_size) {
    const float* x    = (const float*)d_in[0];
    const float* W    = (const float*)d_in[1];
    const float* bias = (const float*)d_in[2];
    const int*   adj  = (const int*)d_in[3];
    const float* zp   = (const float*)d_in[4];
    float* out = (float*)d_out;

    int xg = (Bq * Nq * Fq) / 32;              // 384000 groups
    int tg = xg + (OUTq * Kq) / 32;            // + 8192
    prep_kernel<<<(tg + 255) / 256, 256>>>(x, W, xg, tg);

    cudaFuncSetAttribute(spiral_mma_kernel,
                         cudaFuncAttributeMaxDynamicSharedMemorySize, SMEM_BYTES);
    spiral_mma_kernel<<<Mtot / BM, 128, SMEM_BYTES>>>(bias, adj, zp, out);
}

// round 7
// speedup vs baseline: 1.0946x; 1.0946x over previous
#include <cuda_runtime.h>
#include <cstdint>

// SpiralConv gather-GEMM, mma.sync TF32. R7: R5 shape (8 warps, 64x32 warp
// tiles, 3-stage cp.async) + compile-time stage indices via 3x-unrolled loop
// so all smem addressing folds to [reg+imm].
// out[m,o] = relu(sum_k A[m,k]*W[o,k] + b[o]) * zp[m%N]; M=96000, K=2048, N=128.

constexpr int Bq = 8, Nq = 12000, Fq = 128, Sq = 16, OUTq = 128;
constexpr int Kq = Sq * Fq;       // 2048
constexpr int Mtot = Bq * Nq;     // 96000
constexpr int BM = 128;
constexpr int NITER = Kq / 32;    // 64 (BK=32)
constexpr int NST = 3;

// Pre-rounded (TF32-RNE), per-32-group permuted copies:
// slot s (float4) of each 32-float group holds k = {(s&3)+16*(s>>2)} + 4j.
__device__ float g_x[Bq * Nq * Fq];
__device__ float g_w[OUTq * Kq];

constexpr int STG = BM * 128;                       // 16384 per tile stage
constexpr int OFF_A = 0;
constexpr int OFF_B = OFF_A + NST * STG;            // 49152
constexpr int OFF_ATAB = OFF_B + NST * STG;         // 98304
constexpr int OFF_BIAS = OFF_ATAB + BM * Sq * 4;    // 106496
constexpr int SMEM_BYTES = OFF_BIAS + OUTq * 4;     // 107008

__device__ __forceinline__ float tf32_rne(float f) {
    uint32_t u;
    asm("cvt.rna.tf32.f32 %0, %1;" : "=r"(u) : "f"(f));
    return __uint_as_float(u);
}

__device__ __forceinline__ void cp_async16(void* sdst, const void* gsrc) {
    unsigned d = (unsigned)__cvta_generic_to_shared(sdst);
    asm volatile("cp.async.cg.shared.global [%0], [%1], 16;" :: "r"(d), "l"(gsrc));
}

// ---- prepass: TF32-RNE round + per-32-group fragment permutation ----
__global__ void prep_kernel(const float* __restrict__ x, const float* __restrict__ W,
                            int xn4, int tot4) {
    int t = blockIdx.x * 256 + threadIdx.x;
    if (t >= tot4) return;
    const float* src;
    float* dst;
    int w4 = t;
    if (t < xn4) { src = x; dst = g_x; }
    else         { src = W; dst = g_w; w4 = t - xn4; }
    int w0 = w4 * 4;
    int s = (w0 >> 2) & 7;
    int c0 = (s & 3) + ((s >> 2) << 4);
    int gb = (w0 & ~31) + c0;
    float4 v;
    v.x = tf32_rne(src[gb]);
    v.y = tf32_rne(src[gb + 4]);
    v.z = tf32_rne(src[gb + 8]);
    v.w = tf32_rne(src[gb + 12]);
    reinterpret_cast<float4*>(dst)[w4] = v;
}

extern __shared__ char smem[];

__global__ __launch_bounds__(256, 2) void spiral_mma_kernel(
    const float* __restrict__ bias,
    const int*   __restrict__ adj,
    const float* __restrict__ zp,
    float*       __restrict__ out)
{
    const int tid = threadIdx.x;
    const int m0 = blockIdx.x * BM;

    uint32_t* atab  = reinterpret_cast<uint32_t*>(smem + OFF_ATAB);
    float*    sbias = reinterpret_cast<float*>(smem + OFF_BIAS);

    for (int i = tid; i < BM * Sq; i += 256) {
        int r = i >> 4, s = i & 15;
        int mm = m0 + r;
        int b = mm / Nq, n = mm - b * Nq;
        atab[i] = (uint32_t)(b * Nq + adj[n * Sq + s]) << 9;
    }
    if (tid < OUTq) sbias[tid] = bias[tid];
    __syncthreads();

    // loader geometry
    const int lr = tid >> 3;
    const int lc = tid & 7;
    const uint32_t* atp = atab + lr * 16;
    int adst[4];
    const char* wsrc[4];
    #pragma unroll
    for (int j = 0; j < 4; ++j) {
        int row = lr + j * 32;
        adst[j] = row * 128 + ((lc ^ ((row & 1) << 2)) << 4);
        wsrc[j] = reinterpret_cast<const char*>(g_w) + row * (Kq * 4) + lc * 16;
    }

    const int lane = tid & 31;
    const int warp = tid >> 5;
    const int wm = (warp & 1) * 64;
    const int wn = (warp >> 1) * 32;
    const int tr = lane >> 2;
    const int tc = lane & 3;
    const int swz = (tr & 1) << 2;
    const int chunk0 = tc ^ swz;
    const int chunk1 = (tc + 4) ^ swz;

    float acc[4][4][4];
    #pragma unroll
    for (int a = 0; a < 4; ++a)
        #pragma unroll
        for (int b2 = 0; b2 < 4; ++b2)
            #pragma unroll
            for (int c = 0; c < 4; ++c) acc[a][b2][c] = 0.f;

    auto load_stage = [&](int stoff, int it2) {
        const int sidx = it2 >> 2;
        const char* gx = reinterpret_cast<const char*>(g_x) + ((it2 & 3) << 7) + lc * 16;
        const int wadv = it2 << 7;
        #pragma unroll
        for (int j = 0; j < 4; ++j)
            cp_async16(smem + OFF_A + stoff + adst[j], gx + atp[512 * j + sidx]);
        #pragma unroll
        for (int j = 0; j < 4; ++j)
            cp_async16(smem + OFF_B + stoff + adst[j], wsrc[j] + wadv);
    };

    load_stage(0, 0);       asm volatile("cp.async.commit_group;");
    load_stage(STG, 1);     asm volatile("cp.async.commit_group;");

    auto step = [&](auto CURc, int it) {
        constexpr int CUR = decltype(CURc)::value;
        constexpr int WST = (CUR + 2) % 3;
        asm volatile("cp.async.wait_group 1;");
        __syncthreads();
        if (it + 2 < NITER) load_stage(WST * STG, it + 2);
        asm volatile("cp.async.commit_group;");

        const float4* A4 = reinterpret_cast<const float4*>(smem + OFF_A + CUR * STG);
        const float4* B4 = reinterpret_cast<const float4*>(smem + OFF_B + CUR * STG);

        #pragma unroll
        for (int h = 0; h < 2; ++h) {
            const int chunk = h ? chunk1 : chunk0;
            float4 bfr[4];
            #pragma unroll
            for (int nt = 0; nt < 4; ++nt)
                bfr[nt] = B4[(wn + nt * 8 + tr) * 8 + chunk];
            #pragma unroll
            for (int mt = 0; mt < 4; ++mt) {
                const int r = wm + mt * 16 + tr;
                float4 alo = A4[r * 8 + chunk];
                float4 ahi = A4[(r + 8) * 8 + chunk];
                uint32_t a0 = __float_as_uint(alo.x), a1 = __float_as_uint(ahi.x);
                uint32_t a2 = __float_as_uint(alo.y), a3 = __float_as_uint(ahi.y);
                #pragma unroll
                for (int nt = 0; nt < 4; ++nt)
                    asm volatile(
                        "mma.sync.aligned.m16n8k8.row.col.f32.tf32.tf32.f32 "
                        "{%0,%1,%2,%3}, {%4,%5,%6,%7}, {%8,%9}, {%0,%1,%2,%3};"
                        : "+f"(acc[mt][nt][0]), "+f"(acc[mt][nt][1]),
                          "+f"(acc[mt][nt][2]), "+f"(acc[mt][nt][3])
                        : "r"(a0), "r"(a1), "r"(a2), "r"(a3),
                          "r"(__float_as_uint(bfr[nt].x)), "r"(__float_as_uint(bfr[nt].y)));
                uint32_t c0 = __float_as_uint(alo.z), c1 = __float_as_uint(ahi.z);
                uint32_t c2 = __float_as_uint(alo.w), c3 = __float_as_uint(ahi.w);
                #pragma unroll
                for (int nt = 0; nt < 4; ++nt)
                    asm volatile(
                        "mma.sync.aligned.m16n8k8.row.col.f32.tf32.tf32.f32 "
                        "{%0,%1,%2,%3}, {%4,%5,%6,%7}, {%8,%9}, {%0,%1,%2,%3};"
                        : "+f"(acc[mt][nt][0]), "+f"(acc[mt][nt][1]),
                          "+f"(acc[mt][nt][2]), "+f"(acc[mt][nt][3])
                        : "r"(c0), "r"(c1), "r"(c2), "r"(c3),
                          "r"(__float_as_uint(bfr[nt].z)), "r"(__float_as_uint(bfr[nt].w)));
            }
        }
    };

    // iter 0 (stage 0), then 21 groups of 3 covering iters 1..63
    step(std::integral_constant<int, 0>{}, 0);
    #pragma unroll 1
    for (int g = 0; g < 21; ++g) {
        int it = 1 + g * 3;
        step(std::integral_constant<int, 1>{}, it);
        step(std::integral_constant<int, 2>{}, it + 1);
        step(std::integral_constant<int, 0>{}, it + 2);
    }

    // ---- epilogue ----
    #pragma unroll
    for (int mt = 0; mt < 4; ++mt) {
        #pragma unroll
        for (int hh = 0; hh < 2; ++hh) {
            int m = m0 + wm + mt * 16 + hh * 8 + tr;
            float z = zp[m % Nq];
            float* orow = out + (long)m * OUTq;
            #pragma unroll
            for (int nt = 0; nt < 4; ++nt) {
                int o = wn + nt * 8 + 2 * tc;
                float v0 = fmaxf(acc[mt][nt][hh * 2 + 0] + sbias[o], 0.f) * z;
                float v1 = fmaxf(acc[mt][nt][hh * 2 + 1] + sbias[o + 1], 0.f) * z;
                *reinterpret_cast<float2*>(orow + o) = make_float2(v0, v1);
            }
        }
    }
}

extern "C" void kernel_launch(void* const* d_in, const int* in_sizes, int n_in,
                              void* d_out, int out_size) {
    const float* x    = (const float*)d_in[0];
    const float* W    = (const float*)d_in[1];
    const float* bias = (const float*)d_in[2];
    const int*   adj  = (const int*)d_in[3];
    const float* zp   = (const float*)d_in[4];
    float* out = (float*)d_out;

    int xn4 = (Bq * Nq * Fq) / 4;
    int tot4 = xn4 + (OUTq * Kq) / 4;
    prep_kernel<<<(tot4 + 255) / 256, 256>>>(x, W, xn4, tot4);

    cudaFuncSetAttribute(spiral_mma_kernel,
                         cudaFuncAttributeMaxDynamicSharedMemorySize, SMEM_BYTES);
    spiral_mma_kernel<<<Mtot / BM, 256, SMEM_BYTES>>>(bias, adj, zp, out);
}